// round 7
// baseline (speedup 1.0000x reference)
#include <cuda_runtime.h>
#include <cuda_bf16.h>

// Cumulative mean over axis 0 of x[8192, 4096] fp32:
//   out[r, c] = (sum_{i<=r} x[i, c]) / (r + 1)
//
// 3-pass scan:
//   k_partial : per-16-row-tile column sums -> g_part (reads x; fills g_inv)
//   k_scan    : in-place inclusive scan of g_part over 512 tiles (L2)
//   k_final   : streaming scan over 32-row tiles, reverse tile order,
//               out = (excl prefix + running) * inv

#define ROWS   8192
#define COLS   4096
#define TPB    256
#define C4     (COLS / 4)            // 1024 float4 per row
#define NCB    (COLS / (TPB * 4))    // 4 column blocks (1024 cols each)

#define T1     16                    // pass-1 tile rows
#define NT1    (ROWS / T1)           // 512 partial tiles

#define T3     32                    // pass-3 tile rows (multiple of T1)
#define NT3    (ROWS / T3)           // 256 final tiles

// Static device scratch (no allocation allowed anywhere).
__device__ float4 g_part[NT1 * C4];  // [tile][col4], 8 MB
__device__ float  g_inv[ROWS];       // 1/(r+1), 32 KB

__device__ __forceinline__ float4 f4_add(float4 a, float4 b) {
    a.x += b.x; a.y += b.y; a.z += b.z; a.w += b.w;
    return a;
}

// ---------------- Pass 1: per-tile partial sums (+ inv table) ----------------
__global__ void __launch_bounds__(TPB)
k_partial(const float* __restrict__ x) {
    const int bx  = blockIdx.x;
    const int rt  = bx / NCB;
    const int cb  = bx % NCB;
    const int tid = threadIdx.x;

    // Fill the reciprocal table from the first 8192 threads.
    const int gt = bx * TPB + tid;
    if (gt < ROWS) g_inv[gt] = 1.0f / (float)(gt + 1);

    const float4* __restrict__ x4 = reinterpret_cast<const float4*>(x);
    const int col4 = cb * TPB + tid;
    const int base = rt * T1 * C4 + col4;

    float4 a0 = make_float4(0.f, 0.f, 0.f, 0.f);
    float4 a1 = a0, a2 = a0, a3 = a0;
#pragma unroll
    for (int r = 0; r < T1; r += 4) {
        float4 v0 = __ldg(&x4[base + (r + 0) * C4]);
        float4 v1 = __ldg(&x4[base + (r + 1) * C4]);
        float4 v2 = __ldg(&x4[base + (r + 2) * C4]);
        float4 v3 = __ldg(&x4[base + (r + 3) * C4]);
        a0 = f4_add(a0, v0);
        a1 = f4_add(a1, v1);
        a2 = f4_add(a2, v2);
        a3 = f4_add(a3, v3);
    }
    g_part[rt * C4 + col4] = f4_add(f4_add(a0, a1), f4_add(a2, a3));
}

// ---------------- Pass 2: scan partials over tiles (in place, L2) ------------
__global__ void __launch_bounds__(TPB)
k_scan() {
    const int t = blockIdx.x * TPB + threadIdx.x;   // 0..1023, one col4 each
    float4 run = make_float4(0.f, 0.f, 0.f, 0.f);
#pragma unroll 8
    for (int rt = 0; rt < NT1; rt++) {
        const int idx = rt * C4 + t;
        run = f4_add(run, g_part[idx]);
        g_part[idx] = run;                           // inclusive prefix
    }
}

// ---------------- Pass 3: streaming final scan + scale + store ---------------
__global__ void __launch_bounds__(TPB)
k_final(const float* __restrict__ x, float* __restrict__ out) {
    const int bx  = blockIdx.x;
    // Reverse tile order: highest tiles were read last by k_partial -> L2-fresh.
    const int rt  = (NT3 - 1) - (bx / NCB);
    const int cb  = bx % NCB;
    const int tid = threadIdx.x;

    const float4* __restrict__ x4 = reinterpret_cast<const float4*>(x);
    float4*       __restrict__ o4 = reinterpret_cast<float4*>(out);
    const int col4 = cb * TPB + tid;
    const int base = rt * T3 * C4 + col4;
    const int row0 = rt * T3;

    // Exclusive prefix for this tile from the pass-1 prefix array.
    // Tile rt covers pass-1 tiles [rt*(T3/T1), ...); exclusive prefix is the
    // inclusive prefix of pass-1 tile (rt*(T3/T1) - 1).
    const int p1 = rt * (T3 / T1) - 1;
    float4 run = (p1 < 0) ? make_float4(0.f, 0.f, 0.f, 0.f)
                          : __ldg(&g_part[p1 * C4 + col4]);

    // Stream in batches of 4 independent loads (MLP=4, regs stay low).
#pragma unroll
    for (int r = 0; r < T3; r += 4) {
        float4 v0 = __ldg(&x4[base + (r + 0) * C4]);
        float4 v1 = __ldg(&x4[base + (r + 1) * C4]);
        float4 v2 = __ldg(&x4[base + (r + 2) * C4]);
        float4 v3 = __ldg(&x4[base + (r + 3) * C4]);

        const float i0 = g_inv[row0 + r + 0];
        const float i1 = g_inv[row0 + r + 1];
        const float i2 = g_inv[row0 + r + 2];
        const float i3 = g_inv[row0 + r + 3];

        float4 o;
        run = f4_add(run, v0);
        o.x = run.x * i0; o.y = run.y * i0; o.z = run.z * i0; o.w = run.w * i0;
        __stcs(&o4[base + (r + 0) * C4], o);

        run = f4_add(run, v1);
        o.x = run.x * i1; o.y = run.y * i1; o.z = run.z * i1; o.w = run.w * i1;
        __stcs(&o4[base + (r + 1) * C4], o);

        run = f4_add(run, v2);
        o.x = run.x * i2; o.y = run.y * i2; o.z = run.z * i2; o.w = run.w * i2;
        __stcs(&o4[base + (r + 2) * C4], o);

        run = f4_add(run, v3);
        o.x = run.x * i3; o.y = run.y * i3; o.z = run.z * i3; o.w = run.w * i3;
        __stcs(&o4[base + (r + 3) * C4], o);
    }
}

extern "C" void kernel_launch(void* const* d_in, const int* in_sizes, int n_in,
                              void* d_out, int out_size) {
    const float* x   = (const float*)d_in[0];
    float*       out = (float*)d_out;

    k_partial<<<NT1 * NCB, TPB>>>(x);
    k_scan<<<C4 / TPB, TPB>>>();
    k_final<<<NT3 * NCB, TPB>>>(x, out);
}